// round 3
// baseline (speedup 1.0000x reference)
#include <cuda_runtime.h>
#include <cuda_bf16.h>

#define SEQ   8192
#define DIM   2048
#define H     16
#define HD    128           // head dim
#define PDIM  512           // proj dim
#define NCH   256           // row-chunks for weighted-sum partials (32 rows each)
#define WROWS (SEQ / NCH)   // 32 rows per chunk
#define NSEG  8             // softmax partial segments

// ---------------- scratch (device globals; no allocation allowed) ----------
__device__ float g_qprojH[H * DIM];          // [h][j]
__device__ float g_logits[SEQ * H];          // [s][h]
__device__ float g_pm[NSEG * H];             // per-seg max
__device__ float g_pz[NSEG * H];             // per-seg sumexp
__device__ float g_smax[H];                  // global max per head
__device__ float g_sinv[H];                  // 1/Z per head
__device__ float g_upart[(size_t)NCH * H * DIM]; // partial weighted sums
__device__ float g_u[H * DIM];               // [h][j]
__device__ float g_x1[DIM];
__device__ float g_h1[PDIM];
__device__ float g_g[PDIM];
__device__ float g_x1out[DIM];

// ---------------- f32x2 packed helpers -------------------------------------
union F2U { unsigned long long u; float2 f; };

__device__ __forceinline__ void ffma2(unsigned long long& d,
                                      unsigned long long a,
                                      unsigned long long b) {
    asm("fma.rn.f32x2 %0, %1, %2, %0;" : "+l"(d) : "l"(a), "l"(b));
}
__device__ __forceinline__ void addf32x2(unsigned long long& d, unsigned long long a) {
    asm("add.rn.f32x2 %0, %0, %1;" : "+l"(d) : "l"(a));
}
__device__ __forceinline__ unsigned long long pack2(float lo, float hi) {
    unsigned long long r;
    asm("mov.b64 %0, {%1, %2};" : "=l"(r) : "f"(lo), "f"(hi));
    return r;
}

// ---------------- reductions ----------------
__device__ __forceinline__ float blockReduceSum(float v) {
    __shared__ float sm[32];
    __syncthreads();
    int lane = threadIdx.x & 31, w = threadIdx.x >> 5;
    #pragma unroll
    for (int o = 16; o > 0; o >>= 1) v += __shfl_xor_sync(0xffffffffu, v, o);
    if (lane == 0) sm[w] = v;
    __syncthreads();
    int nw = blockDim.x >> 5;
    v = (threadIdx.x < nw) ? sm[threadIdx.x] : 0.f;
    if (w == 0) {
        #pragma unroll
        for (int o = 16; o > 0; o >>= 1) v += __shfl_xor_sync(0xffffffffu, v, o);
        if (lane == 0) sm[0] = v;
    }
    __syncthreads();
    return sm[0];
}

__device__ __forceinline__ float blockReduceMax(float v) {
    __shared__ float sm[32];
    __syncthreads();
    int lane = threadIdx.x & 31, w = threadIdx.x >> 5;
    #pragma unroll
    for (int o = 16; o > 0; o >>= 1) v = fmaxf(v, __shfl_xor_sync(0xffffffffu, v, o));
    if (lane == 0) sm[w] = v;
    __syncthreads();
    int nw = blockDim.x >> 5;
    v = (threadIdx.x < nw) ? sm[threadIdx.x] : -3.0e38f;
    if (w == 0) {
        #pragma unroll
        for (int o = 16; o > 0; o >>= 1) v = fmaxf(v, __shfl_xor_sync(0xffffffffu, v, o));
        if (lane == 0) sm[0] = v;
    }
    __syncthreads();
    return sm[0];
}

// ---------------- K1: qprojH[h][j] = sum_d q[h*128+d] * W_kv[h*128+d][j] ---
__global__ void k_qproj(const float* __restrict__ q, const float* __restrict__ Wkv) {
    int h  = blockIdx.x >> 3;
    int jb = blockIdx.x & 7;
    int j  = jb * 256 + threadIdx.x;
    __shared__ float sq[HD];
    if (threadIdx.x < HD) sq[threadIdx.x] = q[h * HD + threadIdx.x];
    __syncthreads();
    float acc = 0.f;
    #pragma unroll 8
    for (int d = 0; d < HD; d++)
        acc += sq[d] * Wkv[(size_t)(h * HD + d) * DIM + j];
    g_qprojH[h * DIM + j] = acc;
}

// ---------------- K2: logits[s][h] = x[s] . qproj[h] / sqrt(128) -----------
// 256 blocks x 256 threads; warp owns 4 rows, packed as two row-pairs (f32x2).
// qproj staged in smem duplicated (w,w) -> conflict-free LDS.64, no packing.
__global__ void __launch_bounds__(256) k_logits(const float* __restrict__ x) {
    __shared__ float2 qs2[H][256];      // 32 KB
    int t = threadIdx.x, lane = t & 31, warp = t >> 5;
    int row0 = blockIdx.x * 32 + warp * 4;

    unsigned long long acc01[H], acc23[H];
    #pragma unroll
    for (int h = 0; h < H; h++) { acc01[h] = 0ull; acc23[h] = 0ull; }

    for (int jt = 0; jt < DIM; jt += 256) {
        __syncthreads();
        #pragma unroll
        for (int r = 0; r < 4; r++) {
            int idx = t + r * 256;      // 0..1023 -> (h, 64 float4 per row)
            int h = idx >> 6;
            int jj = idx & 63;
            float4 v = __ldg((const float4*)(g_qprojH + (size_t)h * DIM + jt) + jj);
            qs2[h][jj * 4 + 0] = make_float2(v.x, v.x);
            qs2[h][jj * 4 + 1] = make_float2(v.y, v.y);
            qs2[h][jj * 4 + 2] = make_float2(v.z, v.z);
            qs2[h][jj * 4 + 3] = make_float2(v.w, v.w);
        }
        __syncthreads();
        #pragma unroll
        for (int i = 0; i < 8; i++) {
            int j = i * 32 + lane;
            const float* xp = x + jt + j;
            float x0 = __ldg(xp + (size_t)(row0 + 0) * DIM);
            float x1 = __ldg(xp + (size_t)(row0 + 1) * DIM);
            float x2 = __ldg(xp + (size_t)(row0 + 2) * DIM);
            float x3 = __ldg(xp + (size_t)(row0 + 3) * DIM);
            unsigned long long xp01 = pack2(x0, x1);
            unsigned long long xp23 = pack2(x2, x3);
            #pragma unroll
            for (int h = 0; h < H; h++) {
                unsigned long long w = *(const unsigned long long*)&qs2[h][j];
                ffma2(acc01[h], w, xp01);
                ffma2(acc23[h], w, xp23);
            }
        }
    }
    const float scale = 0.08838834764831845f; // 1/sqrt(128)
    unsigned long long k01 = 0ull, k23 = 0ull;
    #pragma unroll
    for (int h = 0; h < H; h++) {
        unsigned long long v01 = acc01[h], v23 = acc23[h];
        #pragma unroll
        for (int o = 16; o > 0; o >>= 1) {
            addf32x2(v01, __shfl_xor_sync(0xffffffffu, v01, o));
            addf32x2(v23, __shfl_xor_sync(0xffffffffu, v23, o));
        }
        if (lane == h) { k01 = v01; k23 = v23; }
    }
    if (lane < H) {
        F2U u01, u23; u01.u = k01; u23.u = k23;
        g_logits[(size_t)(row0 + 0) * H + lane] = u01.f.x * scale;
        g_logits[(size_t)(row0 + 1) * H + lane] = u01.f.y * scale;
        g_logits[(size_t)(row0 + 2) * H + lane] = u23.f.x * scale;
        g_logits[(size_t)(row0 + 3) * H + lane] = u23.f.y * scale;
    }
}

// ---------------- K3a: per-(head,segment) partial max & sumexp -------------
// grid 16*NSEG blocks x 256 threads; segment = SEQ/NSEG rows
__global__ void k_smax_part() {
    int h   = blockIdx.x >> 3;
    int seg = blockIdx.x & (NSEG - 1);
    int s0  = seg * (SEQ / NSEG);
    float m = -3.0e38f;
    for (int i = threadIdx.x; i < SEQ / NSEG; i += 256)
        m = fmaxf(m, g_logits[(size_t)(s0 + i) * H + h]);
    m = blockReduceMax(m);
    float z = 0.f;
    for (int i = threadIdx.x; i < SEQ / NSEG; i += 256)
        z += __expf(g_logits[(size_t)(s0 + i) * H + h] - m);
    z = blockReduceSum(z);
    if (threadIdx.x == 0) { g_pm[seg * H + h] = m; g_pz[seg * H + h] = z; }
}

// ---------------- K3b: combine partials -> global (max, 1/Z) per head -----
__global__ void k_smax_comb() {
    int t = threadIdx.x;
    if (t < H) {
        float m = -3.0e38f;
        #pragma unroll
        for (int g = 0; g < NSEG; g++) m = fmaxf(m, g_pm[g * H + t]);
        float Z = 0.f;
        #pragma unroll
        for (int g = 0; g < NSEG; g++) Z += g_pz[g * H + t] * __expf(g_pm[g * H + t] - m);
        g_smax[t] = m;
        g_sinv[t] = 1.f / Z;
    }
}

// ---------------- K4: u_part[c][h][j] = sum_{s in chunk} attn[s][h]*x[s][j]
// grid (2 col-tiles, NCH chunks), 256 threads; thread owns 4 cols (float4);
// softmax weights computed inline from logits; head-pairs packed f32x2.
__global__ void __launch_bounds__(256) k_wsum(const float* __restrict__ x) {
    __shared__ float sa[WROWS * H];     // 32 rows x 16 heads = 2 KB
    __shared__ float sm_m[H], sm_z[H];
    int t = threadIdx.x;
    int j4 = blockIdx.x * 256 + t;
    int s0 = blockIdx.y * WROWS;

    if (t < H) { sm_m[t] = g_smax[t]; sm_z[t] = g_sinv[t]; }
    __syncthreads();
    if (t < WROWS * H / 4) {            // 128 float4 loads of logits chunk
        float4 l = __ldg((const float4*)(g_logits + (size_t)s0 * H) + t);
        int h0 = (t & 3) * 4;
        float4 w;
        w.x = __expf(l.x - sm_m[h0 + 0]) * sm_z[h0 + 0];
        w.y = __expf(l.y - sm_m[h0 + 1]) * sm_z[h0 + 1];
        w.z = __expf(l.z - sm_m[h0 + 2]) * sm_z[h0 + 2];
        w.w = __expf(l.w - sm_m[h0 + 3]) * sm_z[h0 + 3];
        ((float4*)sa)[t] = w;
    }
    __syncthreads();

    unsigned long long acc[8][4];       // [head-pair][col]
    #pragma unroll
    for (int hp = 0; hp < 8; hp++)
        #pragma unroll
        for (int c = 0; c < 4; c++) acc[hp][c] = 0ull;

    const float4* x4 = (const float4*)x;
    #pragma unroll 4
    for (int r = 0; r < WROWS; r++) {
        float4 xv = __ldg(x4 + (size_t)(s0 + r) * (DIM / 4) + j4);
        unsigned long long xp[4];
        xp[0] = pack2(xv.x, xv.x);
        xp[1] = pack2(xv.y, xv.y);
        xp[2] = pack2(xv.z, xv.z);
        xp[3] = pack2(xv.w, xv.w);
        const float2* arow = (const float2*)(sa + r * H);
        #pragma unroll
        for (int hp = 0; hp < 8; hp++) {
            float2 a = arow[hp];        // broadcast LDS.64
            unsigned long long ap = pack2(a.x, a.y);
            ffma2(acc[hp][0], ap, xp[0]);
            ffma2(acc[hp][1], ap, xp[1]);
            ffma2(acc[hp][2], ap, xp[2]);
            ffma2(acc[hp][3], ap, xp[3]);
        }
    }
    float* up = g_upart + (size_t)blockIdx.y * (H * DIM);
    #pragma unroll
    for (int hp = 0; hp < 8; hp++) {
        F2U u0, u1, u2, u3;
        u0.u = acc[hp][0]; u1.u = acc[hp][1]; u2.u = acc[hp][2]; u3.u = acc[hp][3];
        float4 lo = make_float4(u0.f.x, u1.f.x, u2.f.x, u3.f.x);
        float4 hi = make_float4(u0.f.y, u1.f.y, u2.f.y, u3.f.y);
        ((float4*)(up + (size_t)(2 * hp + 0) * DIM))[j4] = lo;
        ((float4*)(up + (size_t)(2 * hp + 1) * DIM))[j4] = hi;
    }
}

// ---------------- K4b: u[i] = sum_c u_part[c][i] ---------------------------
__global__ void k_ured() {
    int i = blockIdx.x * 256 + threadIdx.x;   // 0 .. H*DIM-1
    float s = 0.f;
    #pragma unroll 8
    for (int c = 0; c < NCH; c++)
        s += g_upart[(size_t)c * (H * DIM) + i];
    g_u[i] = s;
}

// ---------------- K5: x1[r] = b_v[r] + W_v[r] . u[r>>7] -------------------
__global__ void k_xv(const float* __restrict__ Wkv, const float* __restrict__ bkv) {
    int r = blockIdx.x;
    const float4* w4 = (const float4*)(Wkv + (size_t)(DIM + r) * DIM);
    const float4* u4 = (const float4*)(g_u + (size_t)(r >> 7) * DIM);
    float acc = 0.f;
    for (int i = threadIdx.x; i < DIM / 4; i += 256) {
        float4 a = __ldg(w4 + i), b = u4[i];
        acc += a.x * b.x + a.y * b.y + a.z * b.z + a.w * b.w;
    }
    acc = blockReduceSum(acc);
    if (threadIdx.x == 0) g_x1[r] = acc + bkv[DIM + r];
}

// ---------------- generic GEMV: out[r] = b[r] + W[r] . v -------------------
__global__ void k_gemv(const float* __restrict__ W, const float* __restrict__ v,
                       const float* __restrict__ b, float* __restrict__ out,
                       int ncols4) {
    int r = blockIdx.x;
    const float4* w4 = (const float4*)(W + (size_t)r * (ncols4 * 4));
    const float4* v4 = (const float4*)v;
    float acc = 0.f;
    for (int i = threadIdx.x; i < ncols4; i += 256) {
        float4 a = __ldg(w4 + i), c = v4[i];
        acc += a.x * c.x + a.y * c.y + a.z * c.z + a.w * c.w;
    }
    acc = blockReduceSum(acc);
    if (threadIdx.x == 0) out[r] = acc + b[r];
}

// ---------------- K6b: LayerNorm + ReLU over h1[512] -----------------------
__global__ void k_ln(const float* __restrict__ ln_w, const float* __restrict__ ln_b) {
    int t = threadIdx.x;
    float v = g_h1[t];
    float mu = blockReduceSum(v) * (1.f / PDIM);
    float d = v - mu;
    float var = blockReduceSum(d * d) * (1.f / PDIM);
    float g = d * rsqrtf(var + 1e-5f) * ln_w[t] + ln_b[t];
    g_g[t] = fmaxf(g, 0.f);
}

// ---------------- K8: out[s][j] = x[s][j] + x1out[j] -----------------------
// each thread: 2 float4, strided by 256 within a 512-float4 block span
__global__ void k_resid(const float* __restrict__ x, float* __restrict__ out) {
    size_t base = (size_t)blockIdx.x * 512 + threadIdx.x;
    #pragma unroll
    for (int r = 0; r < 2; r++) {
        size_t i = base + r * 256;
        float4 xv = ((const float4*)x)[i];
        float4 a  = __ldg((const float4*)g_x1out + (i & (DIM / 4 - 1)));
        xv.x += a.x; xv.y += a.y; xv.z += a.z; xv.w += a.w;
        ((float4*)out)[i] = xv;
    }
}

extern "C" void kernel_launch(void* const* d_in, const int* in_sizes, int n_in,
                              void* d_out, int out_size) {
    const float* x    = (const float*)d_in[0];
    const float* q    = (const float*)d_in[1];
    const float* Wkv  = (const float*)d_in[2];
    const float* bkv  = (const float*)d_in[3];
    const float* Wp1  = (const float*)d_in[4];
    const float* bp1  = (const float*)d_in[5];
    const float* Wp2  = (const float*)d_in[6];
    const float* bp2  = (const float*)d_in[7];
    const float* lnw  = (const float*)d_in[8];
    const float* lnb  = (const float*)d_in[9];
    float* out = (float*)d_out;

    float* d_x1;    cudaGetSymbolAddress((void**)&d_x1,    g_x1);
    float* d_h1;    cudaGetSymbolAddress((void**)&d_h1,    g_h1);
    float* d_g;     cudaGetSymbolAddress((void**)&d_g,     g_g);
    float* d_x1out; cudaGetSymbolAddress((void**)&d_x1out, g_x1out);

    k_qproj    <<<128, 256>>>(q, Wkv);
    k_logits   <<<SEQ / 32, 256>>>(x);
    k_smax_part<<<H * NSEG, 256>>>();
    k_smax_comb<<<1, 32>>>();
    {
        dim3 grid(DIM / 4 / 256, NCH);
        k_wsum<<<grid, 256>>>(x);
    }
    k_ured   <<<H * DIM / 256, 256>>>();
    k_xv     <<<DIM, 256>>>(Wkv, bkv);
    k_gemv   <<<PDIM, 256>>>(Wp1, d_x1, bp1, d_h1, DIM / 4);
    k_ln     <<<1, PDIM>>>(lnw, lnb);
    k_gemv   <<<DIM, 256>>>(Wp2, d_g, bp2, d_x1out, PDIM / 4);
    k_resid  <<<SEQ * DIM / 4 / 512, 256>>>(x, out);
}

// round 4
// speedup vs baseline: 1.0641x; 1.0641x over previous
#include <cuda_runtime.h>
#include <cuda_bf16.h>

#define SEQ   8192
#define DIM   2048
#define H     16
#define HD    128           // head dim
#define PDIM  512           // proj dim
#define NCH   128           // row-chunks for weighted-sum partials (64 rows each)
#define WROWS (SEQ / NCH)   // 64 rows per chunk
#define NSEG  (SEQ / 32)    // softmax partial segments = one per logits block (256)

// ---------------- scratch (device globals; no allocation allowed) ----------
__device__ float g_qprojH[H * DIM];          // [h][j]
__device__ float g_logits[SEQ * H];          // [s][h]
__device__ float g_pm[NSEG * H];             // per-seg max
__device__ float g_pz[NSEG * H];             // per-seg sumexp
__device__ float g_upart[(size_t)NCH * H * DIM]; // partial weighted sums
__device__ float g_u[H * DIM];               // [h][j]
__device__ float g_x1[DIM];
__device__ float g_h1[PDIM];
__device__ float g_x1out[DIM];

// ---------------- f32x2 packed helpers -------------------------------------
union F2U { unsigned long long u; float2 f; };

__device__ __forceinline__ void ffma2(unsigned long long& d,
                                      unsigned long long a,
                                      unsigned long long b) {
    asm("fma.rn.f32x2 %0, %1, %2, %0;" : "+l"(d) : "l"(a), "l"(b));
}
__device__ __forceinline__ void addf32x2(unsigned long long& d, unsigned long long a) {
    asm("add.rn.f32x2 %0, %0, %1;" : "+l"(d) : "l"(a));
}
__device__ __forceinline__ unsigned long long pack2(float lo, float hi) {
    unsigned long long r;
    asm("mov.b64 %0, {%1, %2};" : "=l"(r) : "f"(lo), "f"(hi));
    return r;
}

// ---------------- reductions ----------------
__device__ __forceinline__ float blockReduceSum(float v) {
    __shared__ float sm[32];
    __syncthreads();
    int lane = threadIdx.x & 31, w = threadIdx.x >> 5;
    #pragma unroll
    for (int o = 16; o > 0; o >>= 1) v += __shfl_xor_sync(0xffffffffu, v, o);
    if (lane == 0) sm[w] = v;
    __syncthreads();
    int nw = blockDim.x >> 5;
    v = (threadIdx.x < nw) ? sm[threadIdx.x] : 0.f;
    if (w == 0) {
        #pragma unroll
        for (int o = 16; o > 0; o >>= 1) v += __shfl_xor_sync(0xffffffffu, v, o);
        if (lane == 0) sm[0] = v;
    }
    __syncthreads();
    return sm[0];
}

__device__ __forceinline__ float warpReduceSum(float v) {
    #pragma unroll
    for (int o = 16; o > 0; o >>= 1) v += __shfl_xor_sync(0xffffffffu, v, o);
    return v;
}

// ---------------- K1: qprojH[h][j] = sum_d q[h*128+d] * W_kv[h*128+d][j] ---
__global__ void k_qproj(const float* __restrict__ q, const float* __restrict__ Wkv) {
    int h  = blockIdx.x >> 3;
    int jb = blockIdx.x & 7;
    int j  = jb * 256 + threadIdx.x;
    __shared__ float sq[HD];
    if (threadIdx.x < HD) sq[threadIdx.x] = q[h * HD + threadIdx.x];
    __syncthreads();
    float acc = 0.f;
    #pragma unroll 8
    for (int d = 0; d < HD; d++)
        acc += sq[d] * Wkv[(size_t)(h * HD + d) * DIM + j];
    g_qprojH[h * DIM + j] = acc;
}

// ---------------- K2: logits[s][h] + per-block softmax partials ------------
// 256 blocks x 256 threads; warp owns 4 rows packed as two row-pairs (f32x2).
// qproj tiled in smem scalar [h][j] (conflict-free LDS.32).
__global__ void __launch_bounds__(256) k_logits(const float* __restrict__ x) {
    __shared__ float qs[H][256];        // 16 KB
    __shared__ float spm[8 * H], spz[8 * H];
    int t = threadIdx.x, lane = t & 31, warp = t >> 5;
    int row0 = blockIdx.x * 32 + warp * 4;

    unsigned long long acc01[H], acc23[H];
    #pragma unroll
    for (int h = 0; h < H; h++) { acc01[h] = 0ull; acc23[h] = 0ull; }

    for (int jt = 0; jt < DIM; jt += 256) {
        __syncthreads();
        #pragma unroll
        for (int r = 0; r < 4; r++) {
            int idx = t + r * 256;      // 0..1023 -> (h, 64 float4 per row)
            int h = idx >> 6;
            int jj = idx & 63;
            ((float4*)qs[h])[jj] =
                __ldg((const float4*)(g_qprojH + (size_t)h * DIM + jt) + jj);
        }
        __syncthreads();
        #pragma unroll
        for (int i = 0; i < 8; i++) {
            int j = i * 32 + lane;
            const float* xp = x + jt + j;
            float x0 = __ldg(xp + (size_t)(row0 + 0) * DIM);
            float x1 = __ldg(xp + (size_t)(row0 + 1) * DIM);
            float x2 = __ldg(xp + (size_t)(row0 + 2) * DIM);
            float x3 = __ldg(xp + (size_t)(row0 + 3) * DIM);
            unsigned long long xp01 = pack2(x0, x1);
            unsigned long long xp23 = pack2(x2, x3);
            #pragma unroll
            for (int h = 0; h < H; h++) {
                float w = qs[h][j];
                unsigned long long wp = pack2(w, w);
                ffma2(acc01[h], wp, xp01);
                ffma2(acc23[h], wp, xp23);
            }
        }
    }
    const float scale = 0.08838834764831845f; // 1/sqrt(128)
    unsigned long long k01 = 0ull, k23 = 0ull;
    #pragma unroll
    for (int h = 0; h < H; h++) {
        unsigned long long v01 = acc01[h], v23 = acc23[h];
        #pragma unroll
        for (int o = 16; o > 0; o >>= 1) {
            addf32x2(v01, __shfl_xor_sync(0xffffffffu, v01, o));
            addf32x2(v23, __shfl_xor_sync(0xffffffffu, v23, o));
        }
        if (lane == h) { k01 = v01; k23 = v23; }
    }
    if (lane < H) {
        F2U u01, u23; u01.u = k01; u23.u = k23;
        float v0 = u01.f.x * scale, v1 = u01.f.y * scale;
        float v2 = u23.f.x * scale, v3 = u23.f.y * scale;
        g_logits[(size_t)(row0 + 0) * H + lane] = v0;
        g_logits[(size_t)(row0 + 1) * H + lane] = v1;
        g_logits[(size_t)(row0 + 2) * H + lane] = v2;
        g_logits[(size_t)(row0 + 3) * H + lane] = v3;
        // per-warp softmax partial over its 4 rows
        float m = fmaxf(fmaxf(v0, v1), fmaxf(v2, v3));
        float z = __expf(v0 - m) + __expf(v1 - m) + __expf(v2 - m) + __expf(v3 - m);
        spm[warp * H + lane] = m;
        spz[warp * H + lane] = z;
    }
    __syncthreads();
    if (t < H) {                        // merge 8 warps -> per-block partial
        float m = spm[t], z = spz[t];
        #pragma unroll
        for (int w = 1; w < 8; w++) {
            float mw = spm[w * H + t], zw = spz[w * H + t];
            float nm = fmaxf(m, mw);
            z = z * __expf(m - nm) + zw * __expf(mw - nm);
            m = nm;
        }
        g_pm[blockIdx.x * H + t] = m;
        g_pz[blockIdx.x * H + t] = z;
    }
}

// ---------------- K3: u_part[c][h][j] = sum_{s in chunk} attn[s][h]*x[s][j]
// grid (2 col-tiles, NCH chunks) x 256 threads; combines softmax partials
// in-block, computes weights inline, f32x2 accumulate, 2-deep LDG prefetch.
__global__ void __launch_bounds__(256) k_wsum(const float* __restrict__ x) {
    __shared__ float sa[WROWS * H];     // 64 x 16 = 4 KB weights
    __shared__ float sm_m[H], sm_inv[H];
    __shared__ float cm[256], cz[256];
    int t = threadIdx.x;

    // stage 1: each thread merges NSEG/16 segment partials for one head
    {
        int h = t & 15, grp = t >> 4;
        float m = -3.0e38f, z = 0.f;
        #pragma unroll 4
        for (int k = 0; k < NSEG / 16; k++) {
            int seg = grp * (NSEG / 16) + k;
            float mw = g_pm[seg * H + h], zw = g_pz[seg * H + h];
            float nm = fmaxf(m, mw);
            z = z * __expf(m - nm) + zw * __expf(mw - nm);
            m = nm;
        }
        cm[t] = m; cz[t] = z;
    }
    __syncthreads();
    if (t < H) {                        // stage 2: merge the 16 groups
        float m = cm[t], z = cz[t];
        #pragma unroll
        for (int g = 1; g < 16; g++) {
            float mw = cm[g * 16 + t], zw = cz[g * 16 + t];
            float nm = fmaxf(m, mw);
            z = z * __expf(m - nm) + zw * __expf(mw - nm);
            m = nm;
        }
        sm_m[t] = m; sm_inv[t] = 1.f / z;
    }
    __syncthreads();

    int j4 = blockIdx.x * 256 + t;
    int s0 = blockIdx.y * WROWS;
    // weights for this 64-row chunk: 1024 floats = 256 float4
    {
        float4 l = __ldg((const float4*)(g_logits + (size_t)s0 * H) + t);
        int h0 = (t & 3) * 4;
        float4 w;
        w.x = __expf(l.x - sm_m[h0 + 0]) * sm_inv[h0 + 0];
        w.y = __expf(l.y - sm_m[h0 + 1]) * sm_inv[h0 + 1];
        w.z = __expf(l.z - sm_m[h0 + 2]) * sm_inv[h0 + 2];
        w.w = __expf(l.w - sm_m[h0 + 3]) * sm_inv[h0 + 3];
        ((float4*)sa)[t] = w;
    }
    __syncthreads();

    unsigned long long acc[8][4];       // [head-pair][col]
    #pragma unroll
    for (int hp = 0; hp < 8; hp++)
        #pragma unroll
        for (int c = 0; c < 4; c++) acc[hp][c] = 0ull;

    const float4* x4 = (const float4*)x;
    float4 p0 = __ldg(x4 + (size_t)(s0 + 0) * (DIM / 4) + j4);
    float4 p1 = __ldg(x4 + (size_t)(s0 + 1) * (DIM / 4) + j4);
    #pragma unroll 2
    for (int r = 0; r < WROWS; r++) {
        float4 xv = p0;
        p0 = p1;
        if (r + 2 < WROWS)
            p1 = __ldg(x4 + (size_t)(s0 + r + 2) * (DIM / 4) + j4);
        unsigned long long xp[4];
        xp[0] = pack2(xv.x, xv.x);
        xp[1] = pack2(xv.y, xv.y);
        xp[2] = pack2(xv.z, xv.z);
        xp[3] = pack2(xv.w, xv.w);
        const float2* arow = (const float2*)(sa + r * H);
        #pragma unroll
        for (int hp = 0; hp < 8; hp++) {
            float2 a = arow[hp];        // broadcast LDS.64
            unsigned long long ap = pack2(a.x, a.y);
            ffma2(acc[hp][0], ap, xp[0]);
            ffma2(acc[hp][1], ap, xp[1]);
            ffma2(acc[hp][2], ap, xp[2]);
            ffma2(acc[hp][3], ap, xp[3]);
        }
    }
    float* up = g_upart + (size_t)blockIdx.y * (H * DIM);
    #pragma unroll
    for (int hp = 0; hp < 8; hp++) {
        F2U u0, u1, u2, u3;
        u0.u = acc[hp][0]; u1.u = acc[hp][1]; u2.u = acc[hp][2]; u3.u = acc[hp][3];
        float4 lo = make_float4(u0.f.x, u1.f.x, u2.f.x, u3.f.x);
        float4 hi = make_float4(u0.f.y, u1.f.y, u2.f.y, u3.f.y);
        ((float4*)(up + (size_t)(2 * hp + 0) * DIM))[j4] = lo;
        ((float4*)(up + (size_t)(2 * hp + 1) * DIM))[j4] = hi;
    }
}

// ---------------- K4: u[i] = sum_c u_part[c][i] ----------------------------
__global__ void k_ured() {
    int i = blockIdx.x * 256 + threadIdx.x;   // 0 .. H*DIM-1
    float s = 0.f;
    #pragma unroll 8
    for (int c = 0; c < NCH; c++)
        s += g_upart[(size_t)c * (H * DIM) + i];
    g_u[i] = s;
}

// ---------------- K5: x1[r] = b_v[r] + W_v[r] . u[r>>7] --------------------
// warp-per-row, 8 rows/block, u[head] staged in smem; grid 256
__global__ void __launch_bounds__(256) k_xv(const float* __restrict__ Wkv,
                                            const float* __restrict__ bkv) {
    __shared__ float su[DIM];
    int t = threadIdx.x, lane = t & 31, warp = t >> 5;
    int r0 = blockIdx.x * 8;
    int h  = r0 >> 7;                   // 8 | 128 so all rows share the head
    #pragma unroll
    for (int i = 0; i < 2; i++)
        ((float4*)su)[t + i * 256] =
            *((const float4*)(g_u + (size_t)h * DIM) + t + i * 256);
    __syncthreads();
    int r = r0 + warp;
    const float4* w4 = (const float4*)(Wkv + (size_t)(DIM + r) * DIM);
    float acc = 0.f;
    #pragma unroll
    for (int i = 0; i < 16; i++) {
        float4 a = __ldg(w4 + i * 32 + lane);
        float4 b = ((float4*)su)[i * 32 + lane];
        acc += a.x * b.x + a.y * b.y + a.z * b.z + a.w * b.w;
    }
    acc = warpReduceSum(acc);
    if (lane == 0) g_x1[r] = acc + bkv[DIM + r];
}

// ---------------- K6: h1[r] = b_p1[r] + W_p1[r] . x1 -----------------------
// warp-per-row, 8 rows/block, x1 staged in smem; grid 64
__global__ void __launch_bounds__(256) k_mlp1(const float* __restrict__ Wp1,
                                              const float* __restrict__ bp1) {
    __shared__ float sv[DIM];
    int t = threadIdx.x, lane = t & 31, warp = t >> 5;
    #pragma unroll
    for (int i = 0; i < 2; i++)
        ((float4*)sv)[t + i * 256] = *((const float4*)g_x1 + t + i * 256);
    __syncthreads();
    int r = blockIdx.x * 8 + warp;
    const float4* w4 = (const float4*)(Wp1 + (size_t)r * DIM);
    float acc = 0.f;
    #pragma unroll
    for (int i = 0; i < 16; i++) {
        float4 a = __ldg(w4 + i * 32 + lane);
        float4 b = ((float4*)sv)[i * 32 + lane];
        acc += a.x * b.x + a.y * b.y + a.z * b.z + a.w * b.w;
    }
    acc = warpReduceSum(acc);
    if (lane == 0) g_h1[r] = acc + bp1[r];
}

// ---------------- K7: LN(h1) -> relu -> x1out = W_p2 . g + b_p2 ------------
// each block recomputes the tiny LN in smem, then warp-per-row; grid 256
__global__ void __launch_bounds__(256) k_mlp2(const float* __restrict__ lnw,
                                              const float* __restrict__ lnb,
                                              const float* __restrict__ Wp2,
                                              const float* __restrict__ bp2) {
    __shared__ float sg[PDIM];
    int t = threadIdx.x, lane = t & 31, warp = t >> 5;
    float v0 = g_h1[t], v1 = g_h1[t + 256];
    float mu = blockReduceSum(v0 + v1) * (1.f / PDIM);
    float d0 = v0 - mu, d1 = v1 - mu;
    float var = blockReduceSum(d0 * d0 + d1 * d1) * (1.f / PDIM);
    float rs = rsqrtf(var + 1e-5f);
    sg[t]       = fmaxf(d0 * rs * lnw[t]       + lnb[t],       0.f);
    sg[t + 256] = fmaxf(d1 * rs * lnw[t + 256] + lnb[t + 256], 0.f);
    __syncthreads();
    int r = blockIdx.x * 8 + warp;
    const float4* w4 = (const float4*)(Wp2 + (size_t)r * PDIM);
    float acc = 0.f;
    #pragma unroll
    for (int i = 0; i < 4; i++) {
        float4 a = __ldg(w4 + i * 32 + lane);
        float4 b = ((float4*)sg)[i * 32 + lane];
        acc += a.x * b.x + a.y * b.y + a.z * b.z + a.w * b.w;
    }
    acc = warpReduceSum(acc);
    if (lane == 0) g_x1out[r] = acc + bp2[r];
}

// ---------------- K8: out[s][j] = x[s][j] + x1out[j] -----------------------
__global__ void k_resid(const float* __restrict__ x, float* __restrict__ out) {
    size_t base = (size_t)blockIdx.x * 512 + threadIdx.x;
    #pragma unroll
    for (int r = 0; r < 2; r++) {
        size_t i = base + r * 256;
        float4 xv = ((const float4*)x)[i];
        float4 a  = __ldg((const float4*)g_x1out + (i & (DIM / 4 - 1)));
        xv.x += a.x; xv.y += a.y; xv.z += a.z; xv.w += a.w;
        ((float4*)out)[i] = xv;
    }
}

extern "C" void kernel_launch(void* const* d_in, const int* in_sizes, int n_in,
                              void* d_out, int out_size) {
    const float* x    = (const float*)d_in[0];
    const float* q    = (const float*)d_in[1];
    const float* Wkv  = (const float*)d_in[2];
    const float* bkv  = (const float*)d_in[3];
    const float* Wp1  = (const float*)d_in[4];
    const float* bp1  = (const float*)d_in[5];
    const float* Wp2  = (const float*)d_in[6];
    const float* bp2  = (const float*)d_in[7];
    const float* lnw  = (const float*)d_in[8];
    const float* lnb  = (const float*)d_in[9];
    float* out = (float*)d_out;

    k_qproj  <<<128, 256>>>(q, Wkv);
    k_logits <<<SEQ / 32, 256>>>(x);
    {
        dim3 grid(DIM / 4 / 256, NCH);
        k_wsum<<<grid, 256>>>(x);
    }
    k_ured   <<<H * DIM / 256, 256>>>();
    k_xv     <<<DIM / 8, 256>>>(Wkv, bkv);
    k_mlp1   <<<PDIM / 8, 256>>>(Wp1, bp1);
    k_mlp2   <<<DIM / 8, 256>>>(lnw, lnb, Wp2, bp2);
    k_resid  <<<SEQ * DIM / 4 / 512, 256>>>(x, out);
}

// round 5
// speedup vs baseline: 1.1007x; 1.0344x over previous
#include <cuda_runtime.h>
#include <cuda_bf16.h>

#define SEQ   8192
#define DIM   2048
#define H     16
#define HD    128           // head dim
#define PDIM  512           // proj dim
#define NCH   128           // row-chunks for weighted-sum partials (64 rows each)
#define WROWS (SEQ / NCH)   // 64 rows per chunk
#define NSEG  (SEQ / 32)    // softmax partial segments = one per logits block (256)
#define CSPLIT 4            // k_ured chunk-split factor

// ---------------- scratch (device globals; no allocation allowed) ----------
__device__ float g_qprojH[H * DIM];          // [h][j]
__device__ float g_logits[SEQ * H];          // [s][h]
__device__ float g_pm[NSEG * H];             // per-seg max
__device__ float g_pz[NSEG * H];             // per-seg sumexp
__device__ float g_upart[(size_t)NCH * H * DIM]; // partial weighted sums
__device__ float g_u2[CSPLIT * H * DIM];     // 4-way partial u
__device__ float g_x1[DIM];
__device__ float g_h1[PDIM];
__device__ float g_x1out[DIM];

// ---------------- f32x2 packed helpers -------------------------------------
union F2U { unsigned long long u; float2 f; };

__device__ __forceinline__ void ffma2(unsigned long long& d,
                                      unsigned long long a,
                                      unsigned long long b) {
    asm("fma.rn.f32x2 %0, %1, %2, %0;" : "+l"(d) : "l"(a), "l"(b));
}
__device__ __forceinline__ void addf32x2(unsigned long long& d, unsigned long long a) {
    asm("add.rn.f32x2 %0, %0, %1;" : "+l"(d) : "l"(a));
}
__device__ __forceinline__ unsigned long long pack2(float lo, float hi) {
    unsigned long long r;
    asm("mov.b64 %0, {%1, %2};" : "=l"(r) : "f"(lo), "f"(hi));
    return r;
}

// ---------------- reductions ----------------
__device__ __forceinline__ float blockReduceSum(float v) {
    __shared__ float sm[32];
    __syncthreads();
    int lane = threadIdx.x & 31, w = threadIdx.x >> 5;
    #pragma unroll
    for (int o = 16; o > 0; o >>= 1) v += __shfl_xor_sync(0xffffffffu, v, o);
    if (lane == 0) sm[w] = v;
    __syncthreads();
    int nw = blockDim.x >> 5;
    v = (threadIdx.x < nw) ? sm[threadIdx.x] : 0.f;
    if (w == 0) {
        #pragma unroll
        for (int o = 16; o > 0; o >>= 1) v += __shfl_xor_sync(0xffffffffu, v, o);
        if (lane == 0) sm[0] = v;
    }
    __syncthreads();
    return sm[0];
}

__device__ __forceinline__ float warpReduceSum(float v) {
    #pragma unroll
    for (int o = 16; o > 0; o >>= 1) v += __shfl_xor_sync(0xffffffffu, v, o);
    return v;
}

// ---------------- K1: qprojH[h][j] = sum_d q[h*128+d] * W_kv[h*128+d][j] ---
__global__ void k_qproj(const float* __restrict__ q, const float* __restrict__ Wkv) {
    int h  = blockIdx.x >> 3;
    int jb = blockIdx.x & 7;
    int j  = jb * 256 + threadIdx.x;
    __shared__ float sq[HD];
    if (threadIdx.x < HD) sq[threadIdx.x] = q[h * HD + threadIdx.x];
    __syncthreads();
    float acc = 0.f;
    #pragma unroll 8
    for (int d = 0; d < HD; d++)
        acc += sq[d] * Wkv[(size_t)(h * HD + d) * DIM + j];
    g_qprojH[h * DIM + j] = acc;
}

// ---------------- K2: logits[s][h] + per-block softmax partials ------------
// 256 blocks x 256 threads; warp owns 4 rows packed as two row-pairs (f32x2).
// qproj tiled in smem scalar [h][j]; x loads software-pipelined (depth 2x4).
__global__ void __launch_bounds__(256) k_logits(const float* __restrict__ x) {
    __shared__ float qs[H][256];        // 16 KB
    __shared__ float spm[8 * H], spz[8 * H];
    int t = threadIdx.x, lane = t & 31, warp = t >> 5;
    int row0 = blockIdx.x * 32 + warp * 4;

    unsigned long long acc01[H], acc23[H];
    #pragma unroll
    for (int h = 0; h < H; h++) { acc01[h] = 0ull; acc23[h] = 0ull; }

    const float* xr0 = x + (size_t)(row0 + 0) * DIM;
    const float* xr1 = x + (size_t)(row0 + 1) * DIM;
    const float* xr2 = x + (size_t)(row0 + 2) * DIM;
    const float* xr3 = x + (size_t)(row0 + 3) * DIM;

    for (int jt = 0; jt < DIM; jt += 256) {
        __syncthreads();
        #pragma unroll
        for (int r = 0; r < 4; r++) {
            int idx = t + r * 256;      // 0..1023 -> (h, 64 float4 per row)
            int h = idx >> 6;
            int jj = idx & 63;
            ((float4*)qs[h])[jj] =
                __ldg((const float4*)(g_qprojH + (size_t)h * DIM + jt) + jj);
        }
        __syncthreads();
        int j0 = jt + lane;
        float c0 = __ldg(xr0 + j0), c1 = __ldg(xr1 + j0);
        float c2 = __ldg(xr2 + j0), c3 = __ldg(xr3 + j0);
        #pragma unroll
        for (int i = 0; i < 8; i++) {
            float n0, n1, n2, n3;
            if (i < 7) {
                int jn = jt + (i + 1) * 32 + lane;
                n0 = __ldg(xr0 + jn); n1 = __ldg(xr1 + jn);
                n2 = __ldg(xr2 + jn); n3 = __ldg(xr3 + jn);
            }
            int j = i * 32 + lane;
            unsigned long long xp01 = pack2(c0, c1);
            unsigned long long xp23 = pack2(c2, c3);
            #pragma unroll
            for (int h = 0; h < H; h++) {
                float w = qs[h][j];
                unsigned long long wp = pack2(w, w);
                ffma2(acc01[h], wp, xp01);
                ffma2(acc23[h], wp, xp23);
            }
            if (i < 7) { c0 = n0; c1 = n1; c2 = n2; c3 = n3; }
        }
    }
    const float scale = 0.08838834764831845f; // 1/sqrt(128)
    unsigned long long k01 = 0ull, k23 = 0ull;
    #pragma unroll
    for (int h = 0; h < H; h++) {
        unsigned long long v01 = acc01[h], v23 = acc23[h];
        #pragma unroll
        for (int o = 16; o > 0; o >>= 1) {
            addf32x2(v01, __shfl_xor_sync(0xffffffffu, v01, o));
            addf32x2(v23, __shfl_xor_sync(0xffffffffu, v23, o));
        }
        if (lane == h) { k01 = v01; k23 = v23; }
    }
    if (lane < H) {
        F2U u01, u23; u01.u = k01; u23.u = k23;
        float v0 = u01.f.x * scale, v1 = u01.f.y * scale;
        float v2 = u23.f.x * scale, v3 = u23.f.y * scale;
        g_logits[(size_t)(row0 + 0) * H + lane] = v0;
        g_logits[(size_t)(row0 + 1) * H + lane] = v1;
        g_logits[(size_t)(row0 + 2) * H + lane] = v2;
        g_logits[(size_t)(row0 + 3) * H + lane] = v3;
        float m = fmaxf(fmaxf(v0, v1), fmaxf(v2, v3));
        float z = __expf(v0 - m) + __expf(v1 - m) + __expf(v2 - m) + __expf(v3 - m);
        spm[warp * H + lane] = m;
        spz[warp * H + lane] = z;
    }
    __syncthreads();
    if (t < H) {                        // merge 8 warps -> per-block partial
        float m = spm[t], z = spz[t];
        #pragma unroll
        for (int w = 1; w < 8; w++) {
            float mw = spm[w * H + t], zw = spz[w * H + t];
            float nm = fmaxf(m, mw);
            z = z * __expf(m - nm) + zw * __expf(mw - nm);
            m = nm;
        }
        g_pm[blockIdx.x * H + t] = m;
        g_pz[blockIdx.x * H + t] = z;
    }
}

// ---------------- K3: u_part[c][h][j] = sum_{s in chunk} attn[s][h]*x[s][j]
// grid (2 col-tiles, NCH chunks) x 256 threads; softmax combine in-block,
// weights inline, f32x2 accumulate, depth-4 LDG prefetch.
__global__ void __launch_bounds__(256) k_wsum(const float* __restrict__ x) {
    __shared__ float sa[WROWS * H];     // 64 x 16 = 4 KB weights
    __shared__ float sm_m[H], sm_inv[H];
    __shared__ float cm[256], cz[256];
    int t = threadIdx.x;

    // stage 1: each thread merges NSEG/16 segment partials for one head
    {
        int h = t & 15, grp = t >> 4;
        float m = -3.0e38f, z = 0.f;
        #pragma unroll 4
        for (int k = 0; k < NSEG / 16; k++) {
            int seg = grp * (NSEG / 16) + k;
            float mw = g_pm[seg * H + h], zw = g_pz[seg * H + h];
            float nm = fmaxf(m, mw);
            z = z * __expf(m - nm) + zw * __expf(mw - nm);
            m = nm;
        }
        cm[t] = m; cz[t] = z;
    }
    __syncthreads();
    if (t < H) {                        // stage 2: merge the 16 groups
        float m = cm[t], z = cz[t];
        #pragma unroll
        for (int g = 1; g < 16; g++) {
            float mw = cm[g * 16 + t], zw = cz[g * 16 + t];
            float nm = fmaxf(m, mw);
            z = z * __expf(m - nm) + zw * __expf(mw - nm);
            m = nm;
        }
        sm_m[t] = m; sm_inv[t] = 1.f / z;
    }
    __syncthreads();

    int j4 = blockIdx.x * 256 + t;
    int s0 = blockIdx.y * WROWS;
    // weights for this 64-row chunk: 1024 floats = 256 float4
    {
        float4 l = __ldg((const float4*)(g_logits + (size_t)s0 * H) + t);
        int h0 = (t & 3) * 4;
        float4 w;
        w.x = __expf(l.x - sm_m[h0 + 0]) * sm_inv[h0 + 0];
        w.y = __expf(l.y - sm_m[h0 + 1]) * sm_inv[h0 + 1];
        w.z = __expf(l.z - sm_m[h0 + 2]) * sm_inv[h0 + 2];
        w.w = __expf(l.w - sm_m[h0 + 3]) * sm_inv[h0 + 3];
        ((float4*)sa)[t] = w;
    }
    __syncthreads();

    unsigned long long acc[8][4];       // [head-pair][col]
    #pragma unroll
    for (int hp = 0; hp < 8; hp++)
        #pragma unroll
        for (int c = 0; c < 4; c++) acc[hp][c] = 0ull;

    const float4* x4 = (const float4*)x;
    float4 pf[4];
    #pragma unroll
    for (int k = 0; k < 4; k++)
        pf[k] = __ldg(x4 + (size_t)(s0 + k) * (DIM / 4) + j4);

    #pragma unroll 4
    for (int r = 0; r < WROWS; r++) {
        float4 xv = pf[r & 3];
        if (r + 4 < WROWS)
            pf[r & 3] = __ldg(x4 + (size_t)(s0 + r + 4) * (DIM / 4) + j4);
        unsigned long long xp[4];
        xp[0] = pack2(xv.x, xv.x);
        xp[1] = pack2(xv.y, xv.y);
        xp[2] = pack2(xv.z, xv.z);
        xp[3] = pack2(xv.w, xv.w);
        const float2* arow = (const float2*)(sa + r * H);
        #pragma unroll
        for (int hp = 0; hp < 8; hp++) {
            float2 a = arow[hp];        // broadcast LDS.64
            unsigned long long ap = pack2(a.x, a.y);
            ffma2(acc[hp][0], ap, xp[0]);
            ffma2(acc[hp][1], ap, xp[1]);
            ffma2(acc[hp][2], ap, xp[2]);
            ffma2(acc[hp][3], ap, xp[3]);
        }
    }
    float* up = g_upart + (size_t)blockIdx.y * (H * DIM);
    #pragma unroll
    for (int hp = 0; hp < 8; hp++) {
        F2U u0, u1, u2, u3;
        u0.u = acc[hp][0]; u1.u = acc[hp][1]; u2.u = acc[hp][2]; u3.u = acc[hp][3];
        float4 lo = make_float4(u0.f.x, u1.f.x, u2.f.x, u3.f.x);
        float4 hi = make_float4(u0.f.y, u1.f.y, u2.f.y, u3.f.y);
        ((float4*)(up + (size_t)(2 * hp + 0) * DIM))[j4] = lo;
        ((float4*)(up + (size_t)(2 * hp + 1) * DIM))[j4] = hi;
    }
}

// ---------------- K4: u2[p][i] = sum_{c in part p} u_part[c][i] ------------
// grid (128, CSPLIT) x 256 threads -> 512 blocks
__global__ void k_ured() {
    int i  = blockIdx.x * 256 + threadIdx.x;   // 0 .. H*DIM-1
    int c0 = blockIdx.y * (NCH / CSPLIT);
    float s = 0.f;
    #pragma unroll 16
    for (int c = 0; c < NCH / CSPLIT; c++)
        s += g_upart[(size_t)(c0 + c) * (H * DIM) + i];
    g_u2[blockIdx.y * (H * DIM) + i] = s;
}

// ---------------- K5: x1[r] = b_v[r] + W_v[r] . u[r>>7] --------------------
// warp-per-row, 8 rows/block; u[head] assembled from 4 partials into smem
__global__ void __launch_bounds__(256) k_xv(const float* __restrict__ Wkv,
                                            const float* __restrict__ bkv) {
    __shared__ float su[DIM];
    int t = threadIdx.x, lane = t & 31, warp = t >> 5;
    int r0 = blockIdx.x * 8;
    int h  = r0 >> 7;                   // 8 | 128 so all rows share the head
    #pragma unroll
    for (int i = 0; i < 2; i++) {
        int idx = t + i * 256;
        float4 a = *((const float4*)(g_u2 + 0 * (H * DIM) + (size_t)h * DIM) + idx);
        float4 b = *((const float4*)(g_u2 + 1 * (H * DIM) + (size_t)h * DIM) + idx);
        float4 c = *((const float4*)(g_u2 + 2 * (H * DIM) + (size_t)h * DIM) + idx);
        float4 d = *((const float4*)(g_u2 + 3 * (H * DIM) + (size_t)h * DIM) + idx);
        float4 s;
        s.x = (a.x + b.x) + (c.x + d.x);
        s.y = (a.y + b.y) + (c.y + d.y);
        s.z = (a.z + b.z) + (c.z + d.z);
        s.w = (a.w + b.w) + (c.w + d.w);
        ((float4*)su)[idx] = s;
    }
    __syncthreads();
    int r = r0 + warp;
    const float4* w4 = (const float4*)(Wkv + (size_t)(DIM + r) * DIM);
    float acc = 0.f;
    #pragma unroll
    for (int i = 0; i < 16; i++) {
        float4 a = __ldg(w4 + i * 32 + lane);
        float4 b = ((float4*)su)[i * 32 + lane];
        acc += a.x * b.x + a.y * b.y + a.z * b.z + a.w * b.w;
    }
    acc = warpReduceSum(acc);
    if (lane == 0) g_x1[r] = acc + bkv[DIM + r];
}

// ---------------- K6: h1[r] = b_p1[r] + W_p1[r] . x1 -----------------------
__global__ void __launch_bounds__(256) k_mlp1(const float* __restrict__ Wp1,
                                              const float* __restrict__ bp1) {
    __shared__ float sv[DIM];
    int t = threadIdx.x, lane = t & 31, warp = t >> 5;
    #pragma unroll
    for (int i = 0; i < 2; i++)
        ((float4*)sv)[t + i * 256] = *((const float4*)g_x1 + t + i * 256);
    __syncthreads();
    int r = blockIdx.x * 8 + warp;
    const float4* w4 = (const float4*)(Wp1 + (size_t)r * DIM);
    float acc = 0.f;
    #pragma unroll
    for (int i = 0; i < 16; i++) {
        float4 a = __ldg(w4 + i * 32 + lane);
        float4 b = ((float4*)sv)[i * 32 + lane];
        acc += a.x * b.x + a.y * b.y + a.z * b.z + a.w * b.w;
    }
    acc = warpReduceSum(acc);
    if (lane == 0) g_h1[r] = acc + bp1[r];
}

// ---------------- K7: LN(h1) -> relu -> x1out = W_p2 . g + b_p2 ------------
__global__ void __launch_bounds__(256) k_mlp2(const float* __restrict__ lnw,
                                              const float* __restrict__ lnb,
                                              const float* __restrict__ Wp2,
                                              const float* __restrict__ bp2) {
    __shared__ float sg[PDIM];
    int t = threadIdx.x, lane = t & 31, warp = t >> 5;
    float v0 = g_h1[t], v1 = g_h1[t + 256];
    float mu = blockReduceSum(v0 + v1) * (1.f / PDIM);
    float d0 = v0 - mu, d1 = v1 - mu;
    float var = blockReduceSum(d0 * d0 + d1 * d1) * (1.f / PDIM);
    float rs = rsqrtf(var + 1e-5f);
    sg[t]       = fmaxf(d0 * rs * lnw[t]       + lnb[t],       0.f);
    sg[t + 256] = fmaxf(d1 * rs * lnw[t + 256] + lnb[t + 256], 0.f);
    __syncthreads();
    int r = blockIdx.x * 8 + warp;
    const float4* w4 = (const float4*)(Wp2 + (size_t)r * PDIM);
    float acc = 0.f;
    #pragma unroll
    for (int i = 0; i < 4; i++) {
        float4 a = __ldg(w4 + i * 32 + lane);
        float4 b = ((float4*)sg)[i * 32 + lane];
        acc += a.x * b.x + a.y * b.y + a.z * b.z + a.w * b.w;
    }
    acc = warpReduceSum(acc);
    if (lane == 0) g_x1out[r] = acc + bp2[r];
}

// ---------------- K8: out[s][j] = x[s][j] + x1out[j] -----------------------
__global__ void k_resid(const float* __restrict__ x, float* __restrict__ out) {
    size_t base = (size_t)blockIdx.x * 512 + threadIdx.x;
    #pragma unroll
    for (int r = 0; r < 2; r++) {
        size_t i = base + r * 256;
        float4 xv = ((const float4*)x)[i];
        float4 a  = __ldg((const float4*)g_x1out + (i & (DIM / 4 - 1)));
        xv.x += a.x; xv.y += a.y; xv.z += a.z; xv.w += a.w;
        ((float4*)out)[i] = xv;
    }
}

extern "C" void kernel_launch(void* const* d_in, const int* in_sizes, int n_in,
                              void* d_out, int out_size) {
    const float* x    = (const float*)d_in[0];
    const float* q    = (const float*)d_in[1];
    const float* Wkv  = (const float*)d_in[2];
    const float* bkv  = (const float*)d_in[3];
    const float* Wp1  = (const float*)d_in[4];
    const float* bp1  = (const float*)d_in[5];
    const float* Wp2  = (const float*)d_in[6];
    const float* bp2  = (const float*)d_in[7];
    const float* lnw  = (const float*)d_in[8];
    const float* lnb  = (const float*)d_in[9];
    float* out = (float*)d_out;

    k_qproj  <<<128, 256>>>(q, Wkv);
    k_logits <<<SEQ / 32, 256>>>(x);
    {
        dim3 grid(DIM / 4 / 256, NCH);
        k_wsum<<<grid, 256>>>(x);
    }
    {
        dim3 grid(H * DIM / 256, CSPLIT);
        k_ured<<<grid, 256>>>();
    }
    k_xv     <<<DIM / 8, 256>>>(Wkv, bkv);
    k_mlp1   <<<PDIM / 8, 256>>>(Wp1, bp1);
    k_mlp2   <<<DIM / 8, 256>>>(lnw, lnb, Wp2, bp2);
    k_resid  <<<SEQ * DIM / 4 / 512, 256>>>(x, out);
}